// round 4
// baseline (speedup 1.0000x reference)
#include <cuda_runtime.h>
#include <mma.h>

using namespace nvcuda;

// ---------------------------------------------------------------------------
// Fused ExtractorMLP, tf32 wmma (HMMA path — tcgen05 unavailable: harness
// compiles PTX at compute_103 which rejects arch-accelerated instructions).
//   f12 = concat(emb[col], emb[row])   [E,256]
//   x1  = relu(f12 @ W1 + b1)          [E,512]  (4 N-chunks of 128, smem-resident)
//   x2  = relu(x1 @ W2 + b2)           [E,128]  (register accumulators)
//   out = x2 @ W3 + b3                 [E,1]
// One CTA = 128 edges, 512 threads (16 warps), warp tile 32x32.
// All MMA operands pre-rounded to tf32 so fragment cvt loops are eliminated.
// ---------------------------------------------------------------------------

#define LDF 264               // f12 leading dim (256 + 8)
#define LDX 136               // x1 chunk leading dim (128 + 8)
#define M_TILE 128
#define THREADS 512

__device__ float g_W1R[256 * 512];   // tf32-rounded W1 [k][n]
__device__ float g_W2R[512 * 128];   // tf32-rounded W2 [k][n]

__device__ __forceinline__ float to_tf32(float x) {
    float r; asm("cvt.rna.tf32.f32 %0, %1;" : "=f"(r) : "f"(x)); return r;
}

__global__ void prep_weights(const float* __restrict__ W1,
                             const float* __restrict__ W2) {
    int i = blockIdx.x * blockDim.x + threadIdx.x;
    if (i < 256 * 512) {
        g_W1R[i] = to_tf32(W1[i]);
    } else {
        int j = i - 256 * 512;
        if (j < 512 * 128) g_W2R[j] = to_tf32(W2[j]);
    }
}

__global__ void __launch_bounds__(THREADS, 1)
extractor_mlp_kernel(const float* __restrict__ emb,
                     const int* __restrict__ edge_index,
                     const float* __restrict__ b1,
                     const float* __restrict__ b2,
                     const float* __restrict__ W3,
                     const float* __restrict__ b3,
                     float* __restrict__ out, int E)
{
    extern __shared__ float smem[];
    float* f12 = smem;                      // [128][LDF]
    float* x1c = smem + M_TILE * LDF;       // [128][LDX] (reused for x2)
    __shared__ int   s_col[M_TILE];
    __shared__ int   s_row[M_TILE];
    __shared__ float b1s[512];
    __shared__ float b2s[128];
    __shared__ float W3s[128];

    const int tid  = threadIdx.x;
    const int base = blockIdx.x * M_TILE;

    // ---- indices + biases into smem --------------------------------------
    if (tid < M_TILE) {
        int e = base + tid;
        s_col[tid] = (e < E) ? edge_index[e] : -1;
    } else if (tid < 2 * M_TILE) {
        int e = base + (tid - M_TILE);
        s_row[tid - M_TILE] = (e < E) ? edge_index[E + e] : -1;
    } else if (tid < 2 * M_TILE + 128) {
        int n = tid - 2 * M_TILE;
        b2s[n] = b2[n];
        W3s[n] = W3[n];
    }
    if (tid < 512) b1s[tid] = b1[tid];  // note: overlaps groups above is fine?  no — keep separate:
    __syncthreads();

    // ---- gather f12 (tf32-rounded at store) -------------------------------
    for (int i = tid; i < M_TILE * 64; i += THREADS) {
        int m = i >> 6;
        int q = i & 63;
        int idx = (q < 32) ? s_col[m] : s_row[m];
        int qq  = (q < 32) ? q : (q - 32);
        float4 v;
        if (idx >= 0)
            v = ((const float4*)(emb + (long long)idx * 128))[qq];
        else
            v = make_float4(0.f, 0.f, 0.f, 0.f);
        v.x = to_tf32(v.x); v.y = to_tf32(v.y);
        v.z = to_tf32(v.z); v.w = to_tf32(v.w);
        *(float4*)(f12 + m * LDF + q * 4) = v;
    }
    __syncthreads();

    // ---- warp tiling: 4 (M) x 4 (N), each warp 32x32 ----------------------
    const int w  = tid >> 5;
    const int wm = (w & 3) * 32;
    const int wn = (w >> 2) * 32;

    wmma::fragment<wmma::accumulator, 16, 16, 8, float> acc2[2][2];
    #pragma unroll
    for (int i = 0; i < 2; ++i)
        #pragma unroll
        for (int j = 0; j < 2; ++j)
            wmma::fill_fragment(acc2[i][j], 0.0f);

    #pragma unroll 1
    for (int c = 0; c < 4; ++c) {
        // ----- layer 1 chunk: acc1 = f12 @ W1R[:, c*128+wn..] --------------
        wmma::fragment<wmma::accumulator, 16, 16, 8, float> acc1[2][2];
        #pragma unroll
        for (int i = 0; i < 2; ++i)
            #pragma unroll
            for (int j = 0; j < 2; ++j)
                wmma::fill_fragment(acc1[i][j], 0.0f);

        #pragma unroll 2
        for (int k = 0; k < 256; k += 8) {
            wmma::fragment<wmma::matrix_b, 16, 16, 8, wmma::precision::tf32, wmma::row_major> bf[2];
            #pragma unroll
            for (int j = 0; j < 2; ++j)
                wmma::load_matrix_sync(bf[j], g_W1R + (size_t)k * 512 + c * 128 + wn + j * 16, 512);
            wmma::fragment<wmma::matrix_a, 16, 16, 8, wmma::precision::tf32, wmma::row_major> a[2];
            #pragma unroll
            for (int i = 0; i < 2; ++i)
                wmma::load_matrix_sync(a[i], f12 + (wm + i * 16) * LDF + k, LDF);
            #pragma unroll
            for (int i = 0; i < 2; ++i)
                #pragma unroll
                for (int j = 0; j < 2; ++j)
                    wmma::mma_sync(acc1[i][j], a[i], bf[j], acc1[i][j]);
        }

        // x1c may still be read by previous chunk's layer 2
        __syncthreads();

        #pragma unroll
        for (int i = 0; i < 2; ++i)
            #pragma unroll
            for (int j = 0; j < 2; ++j)
                wmma::store_matrix_sync(x1c + (wm + i * 16) * LDX + wn + j * 16,
                                        acc1[i][j], LDX, wmma::mem_row_major);
        __syncthreads();

        // ----- bias + relu + tf32 round (in smem) --------------------------
        for (int i = tid; i < 128 * 32; i += THREADS) {
            int m = i >> 5;            // edge row
            int nq = i & 31;           // float4 group
            float4 v = *(float4*)(x1c + m * LDX + nq * 4);
            const float* bb = b1s + c * 128 + nq * 4;
            v.x = to_tf32(fmaxf(v.x + bb[0], 0.f));
            v.y = to_tf32(fmaxf(v.y + bb[1], 0.f));
            v.z = to_tf32(fmaxf(v.z + bb[2], 0.f));
            v.w = to_tf32(fmaxf(v.w + bb[3], 0.f));
            *(float4*)(x1c + m * LDX + nq * 4) = v;
        }
        __syncthreads();

        // ----- layer 2 partial: acc2 += x1c @ W2R[c*128.., wn..] -----------
        #pragma unroll 2
        for (int k = 0; k < 128; k += 8) {
            wmma::fragment<wmma::matrix_b, 16, 16, 8, wmma::precision::tf32, wmma::row_major> bf[2];
            #pragma unroll
            for (int j = 0; j < 2; ++j)
                wmma::load_matrix_sync(bf[j], g_W2R + (size_t)(c * 128 + k) * 128 + wn + j * 16, 128);
            wmma::fragment<wmma::matrix_a, 16, 16, 8, wmma::precision::tf32, wmma::row_major> a[2];
            #pragma unroll
            for (int i = 0; i < 2; ++i)
                wmma::load_matrix_sync(a[i], x1c + (wm + i * 16) * LDX + k, LDX);
            #pragma unroll
            for (int i = 0; i < 2; ++i)
                #pragma unroll
                for (int j = 0; j < 2; ++j)
                    wmma::mma_sync(acc2[i][j], a[i], bf[j], acc2[i][j]);
        }
    }

    // ---- x2 -> smem -------------------------------------------------------
    __syncthreads();
    #pragma unroll
    for (int i = 0; i < 2; ++i)
        #pragma unroll
        for (int j = 0; j < 2; ++j)
            wmma::store_matrix_sync(x1c + (wm + i * 16) * LDX + wn + j * 16,
                                    acc2[i][j], LDX, wmma::mem_row_major);
    __syncthreads();

    // ---- layer 3: 4 threads per edge -------------------------------------
    {
        int m = tid >> 2;
        int h = tid & 3;
        const float* xr = x1c + m * LDX + h * 32;
        const float* bb = b2s + h * 32;
        const float* ww = W3s + h * 32;
        float s = 0.0f;
        #pragma unroll 8
        for (int n = 0; n < 32; ++n) {
            float v = fmaxf(xr[n] + bb[n], 0.0f);
            s += v * ww[n];
        }
        s += __shfl_xor_sync(0xffffffffu, s, 1);
        s += __shfl_xor_sync(0xffffffffu, s, 2);
        int e = base + m;
        if (h == 0 && e < E)
            out[e] = s + __ldg(b3);
    }
}

extern "C" void kernel_launch(void* const* d_in, const int* in_sizes, int n_in,
                              void* d_out, int out_size)
{
    const float* emb = (const float*)d_in[0];
    const int*   ei  = (const int*)d_in[1];     // int32 (JAX x64 disabled)
    const float* W1  = (const float*)d_in[2];
    const float* b1  = (const float*)d_in[3];
    const float* W2  = (const float*)d_in[4];
    const float* b2  = (const float*)d_in[5];
    const float* W3  = (const float*)d_in[6];
    const float* b3  = (const float*)d_in[7];
    float* out = (float*)d_out;

    const int E = out_size;   // output is [E,1] float32

    prep_weights<<<(256*512 + 512*128 + 255) / 256, 256>>>(W1, W2);

    size_t smem_bytes = (size_t)(M_TILE * LDF + M_TILE * LDX) * sizeof(float);
    cudaFuncSetAttribute(extractor_mlp_kernel,
                         cudaFuncAttributeMaxDynamicSharedMemorySize,
                         (int)smem_bytes);

    int grid = (E + M_TILE - 1) / M_TILE;
    extractor_mlp_kernel<<<grid, THREADS, smem_bytes>>>(
        emb, ei, b1, b2, W3, b3, out, E);
}

// round 5
// speedup vs baseline: 2.0522x; 2.0522x over previous
#include <cuda_runtime.h>
#include <cuda_fp16.h>
#include <mma.h>

using namespace nvcuda;

// ---------------------------------------------------------------------------
// Fused ExtractorMLP, fp16 wmma (m16n16k16, HMMA) with fp32 accumulate.
// fp16 mantissa == tf32 mantissa (10 bits) -> same accuracy as the tf32 run
// (measured 4.3e-4), but 2x FLOP/instr and 1/2 operand bytes.
//   f12 = concat(emb[col], emb[row])   [E,256]   (half, smem)
//   x1  = relu(f12 @ W1 + b1)          [E,512]   (4 N-chunks of 128)
//   x2  = relu(x1 @ W2 + b2)           [E,128]   (fp32 reg accumulators)
//   out = x2 @ W3 + b3                 [E,1]
// One CTA = 128 edges, 256 threads (8 warps), warp tile 64x32.
// ---------------------------------------------------------------------------

#define M_TILE  128
#define THREADS 256
#define LDF 272          // f12 leading dim in halves (256 + 16)
#define LDS 136          // fp32 staging leading dim in floats (128 + 8)
#define LDX 144          // x1 half leading dim in halves (128 + 16)

#define SZ_F12 (M_TILE * LDF * 2)        // 69632
#define SZ_STG (M_TILE * LDS * 4)        // 69632
#define SZ_X1H (M_TILE * LDX * 2)        // 36864
#define SMEM_DYN (SZ_F12 + SZ_STG + SZ_X1H)

__device__ __half g_W1H[256 * 512];   // [k][n]
__device__ __half g_W2H[512 * 128];   // [k][n]

__global__ void prep_weights(const float* __restrict__ W1,
                             const float* __restrict__ W2) {
    int i = blockIdx.x * blockDim.x + threadIdx.x;
    if (i < 256 * 512) {
        g_W1H[i] = __float2half_rn(W1[i]);
    } else {
        int j = i - 256 * 512;
        if (j < 512 * 128) g_W2H[j] = __float2half_rn(W2[j]);
    }
}

__global__ void __launch_bounds__(THREADS, 1)
extractor_mlp_kernel(const float* __restrict__ emb,
                     const int* __restrict__ edge_index,
                     const float* __restrict__ b1,
                     const float* __restrict__ b2,
                     const float* __restrict__ W3,
                     const float* __restrict__ b3,
                     float* __restrict__ out, int E)
{
    extern __shared__ char smem[];
    __half* f12 = (__half*)smem;                      // [128][LDF] half
    float*  stg = (float*)(smem + SZ_F12);            // [128][LDS] fp32
    __half* x1h = (__half*)(smem + SZ_F12 + SZ_STG);  // [128][LDX] half

    __shared__ int   s_col[M_TILE];
    __shared__ int   s_row[M_TILE];
    __shared__ float b1s[512];
    __shared__ float b2s[128];
    __shared__ float W3s[128];

    const int tid  = threadIdx.x;
    const int base = blockIdx.x * M_TILE;

    // ---- indices + biases -------------------------------------------------
    if (tid < M_TILE) {
        int e = base + tid;
        s_col[tid] = (e < E) ? edge_index[e] : -1;
        int e2 = base + tid;
        s_row[tid] = (e2 < E) ? edge_index[E + e2] : -1;
    } else {
        int n = tid - M_TILE;
        b2s[n] = b2[n];
        W3s[n] = W3[n];
    }
    {
        int n = tid * 2;
        b1s[n]     = b1[n];
        b1s[n + 1] = b1[n + 1];
    }
    __syncthreads();

    // ---- gather f12 as half ------------------------------------------------
    for (int i = tid; i < M_TILE * 64; i += THREADS) {
        int m = i >> 6;
        int q = i & 63;                 // float4 group within 256-float row
        int idx = (q < 32) ? s_col[m] : s_row[m];
        int qq  = (q < 32) ? q : (q - 32);
        float4 v;
        if (idx >= 0)
            v = ((const float4*)(emb + (long long)idx * 128))[qq];
        else
            v = make_float4(0.f, 0.f, 0.f, 0.f);
        __half2* dst = (__half2*)(f12 + m * LDF + q * 4);
        dst[0] = __floats2half2_rn(v.x, v.y);
        dst[1] = __floats2half2_rn(v.z, v.w);
    }
    __syncthreads();

    // ---- warp tiling: 2 (M) x 4 (N); warp tile 64x32 ----------------------
    const int w  = tid >> 5;
    const int wm = (w & 1) * 64;
    const int wn = (w >> 1) * 32;

    wmma::fragment<wmma::accumulator, 16, 16, 16, float> acc2[4][2];
    #pragma unroll
    for (int i = 0; i < 4; ++i)
        #pragma unroll
        for (int j = 0; j < 2; ++j)
            wmma::fill_fragment(acc2[i][j], 0.0f);

    #pragma unroll 1
    for (int c = 0; c < 4; ++c) {
        // ----- layer 1 chunk: acc1 = f12 @ W1H[:, c*128 + wn..] -----------
        wmma::fragment<wmma::accumulator, 16, 16, 16, float> acc1[4][2];
        #pragma unroll
        for (int i = 0; i < 4; ++i)
            #pragma unroll
            for (int j = 0; j < 2; ++j)
                wmma::fill_fragment(acc1[i][j], 0.0f);

        #pragma unroll 2
        for (int k = 0; k < 256; k += 16) {
            wmma::fragment<wmma::matrix_b, 16, 16, 16, __half, wmma::row_major> bf[2];
            #pragma unroll
            for (int j = 0; j < 2; ++j)
                wmma::load_matrix_sync(bf[j], g_W1H + (size_t)k * 512 + c * 128 + wn + j * 16, 512);
            wmma::fragment<wmma::matrix_a, 16, 16, 16, __half, wmma::row_major> a[4];
            #pragma unroll
            for (int i = 0; i < 4; ++i)
                wmma::load_matrix_sync(a[i], f12 + (wm + i * 16) * LDF + k, LDF);
            #pragma unroll
            for (int i = 0; i < 4; ++i)
                #pragma unroll
                for (int j = 0; j < 2; ++j)
                    wmma::mma_sync(acc1[i][j], a[i], bf[j], acc1[i][j]);
        }

        // x1h may still be read by previous chunk's layer 2
        __syncthreads();

        #pragma unroll
        for (int i = 0; i < 4; ++i)
            #pragma unroll
            for (int j = 0; j < 2; ++j)
                wmma::store_matrix_sync(stg + (wm + i * 16) * LDS + wn + j * 16,
                                        acc1[i][j], LDS, wmma::mem_row_major);
        __syncthreads();

        // ----- bias + relu, fp32 staging -> half x1h -----------------------
        for (int i = tid; i < 128 * 32; i += THREADS) {
            int m  = i >> 5;
            int nq = i & 31;            // 4-float group within 128
            float4 v = *(float4*)(stg + m * LDS + nq * 4);
            const float* bb = b1s + c * 128 + nq * 4;
            float r0 = fmaxf(v.x + bb[0], 0.f);
            float r1 = fmaxf(v.y + bb[1], 0.f);
            float r2 = fmaxf(v.z + bb[2], 0.f);
            float r3 = fmaxf(v.w + bb[3], 0.f);
            __half2* dst = (__half2*)(x1h + m * LDX + nq * 4);
            dst[0] = __floats2half2_rn(r0, r1);
            dst[1] = __floats2half2_rn(r2, r3);
        }
        __syncthreads();

        // ----- layer 2 partial: acc2 += x1h @ W2H[c*128.., wn..] -----------
        #pragma unroll 2
        for (int k = 0; k < 128; k += 16) {
            wmma::fragment<wmma::matrix_b, 16, 16, 16, __half, wmma::row_major> bf[2];
            #pragma unroll
            for (int j = 0; j < 2; ++j)
                wmma::load_matrix_sync(bf[j], g_W2H + (size_t)(c * 128 + k) * 128 + wn + j * 16, 128);
            wmma::fragment<wmma::matrix_a, 16, 16, 16, __half, wmma::row_major> a[4];
            #pragma unroll
            for (int i = 0; i < 4; ++i)
                wmma::load_matrix_sync(a[i], x1h + (wm + i * 16) * LDX + k, LDX);
            #pragma unroll
            for (int i = 0; i < 4; ++i)
                #pragma unroll
                for (int j = 0; j < 2; ++j)
                    wmma::mma_sync(acc2[i][j], a[i], bf[j], acc2[i][j]);
        }
    }

    // ---- x2 (fp32) -> staging ----------------------------------------------
    __syncthreads();
    #pragma unroll
    for (int i = 0; i < 4; ++i)
        #pragma unroll
        for (int j = 0; j < 2; ++j)
            wmma::store_matrix_sync(stg + (wm + i * 16) * LDS + wn + j * 16,
                                    acc2[i][j], LDS, wmma::mem_row_major);
    __syncthreads();

    // ---- layer 3: 2 threads per edge ---------------------------------------
    {
        int m = tid >> 1;
        int h = tid & 1;
        const float* xr = stg + m * LDS + h * 64;
        const float* bb = b2s + h * 64;
        const float* ww = W3s + h * 64;
        float s = 0.0f;
        #pragma unroll 8
        for (int n = 0; n < 64; ++n) {
            float v = fmaxf(xr[n] + bb[n], 0.0f);
            s += v * ww[n];
        }
        s += __shfl_xor_sync(0xffffffffu, s, 1);
        int e = base + m;
        if (h == 0 && e < E)
            out[e] = s + __ldg(b3);
    }
}

extern "C" void kernel_launch(void* const* d_in, const int* in_sizes, int n_in,
                              void* d_out, int out_size)
{
    const float* emb = (const float*)d_in[0];
    const int*   ei  = (const int*)d_in[1];     // int32 (JAX x64 disabled)
    const float* W1  = (const float*)d_in[2];
    const float* b1  = (const float*)d_in[3];
    const float* W2  = (const float*)d_in[4];
    const float* b2  = (const float*)d_in[5];
    const float* W3  = (const float*)d_in[6];
    const float* b3  = (const float*)d_in[7];
    float* out = (float*)d_out;

    const int E = out_size;   // output is [E,1] float32

    prep_weights<<<(256*512 + 512*128 + 255) / 256, 256>>>(W1, W2);

    cudaFuncSetAttribute(extractor_mlp_kernel,
                         cudaFuncAttributeMaxDynamicSharedMemorySize, SMEM_DYN);

    int grid = (E + M_TILE - 1) / M_TILE;
    extractor_mlp_kernel<<<grid, THREADS, SMEM_DYN>>>(
        emb, ei, b1, b2, W3, b3, out, E);
}

// round 6
// speedup vs baseline: 2.1845x; 1.0645x over previous
#include <cuda_runtime.h>
#include <cuda_fp16.h>
#include <mma.h>

using namespace nvcuda;

// ---------------------------------------------------------------------------
// Fused ExtractorMLP, fp16 wmma (m16n16k16) with fp32 accumulate.
// Round 6: conflict-free smem leading dims. ldmatrix needs row_stride mod 128B
// == 16B so the 8 row addresses per phase sweep all eight 16B bank slots:
//   LDF = 264 halves (528B), LDX = 136 halves (272B), LDS = 132 floats (528B).
// Previous dims (544B/288B/544B) were mod-128 == 32 -> 2-way conflicts on
// every LDSM/store. Everything else identical to the 2314us round-5 kernel.
// ---------------------------------------------------------------------------

#define M_TILE  128
#define THREADS 256
#define LDF 264          // f12 leading dim in halves  (row stride 528B)
#define LDS 132          // fp32 staging leading dim   (row stride 528B)
#define LDX 136          // x1 half leading dim        (row stride 272B)

#define SZ_F12 (M_TILE * LDF * 2)        // 67584
#define SZ_STG (M_TILE * LDS * 4)        // 67584
#define SZ_X1H (M_TILE * LDX * 2)        // 34816
#define SMEM_DYN (SZ_F12 + SZ_STG + SZ_X1H)

__device__ __half g_W1H[256 * 512];   // [k][n]
__device__ __half g_W2H[512 * 128];   // [k][n]

__global__ void prep_weights(const float* __restrict__ W1,
                             const float* __restrict__ W2) {
    int i = blockIdx.x * blockDim.x + threadIdx.x;
    if (i < 256 * 512) {
        g_W1H[i] = __float2half_rn(W1[i]);
    } else {
        int j = i - 256 * 512;
        if (j < 512 * 128) g_W2H[j] = __float2half_rn(W2[j]);
    }
}

__global__ void __launch_bounds__(THREADS, 1)
extractor_mlp_kernel(const float* __restrict__ emb,
                     const int* __restrict__ edge_index,
                     const float* __restrict__ b1,
                     const float* __restrict__ b2,
                     const float* __restrict__ W3,
                     const float* __restrict__ b3,
                     float* __restrict__ out, int E)
{
    extern __shared__ char smem[];
    __half* f12 = (__half*)smem;                      // [128][LDF] half
    float*  stg = (float*)(smem + SZ_F12);            // [128][LDS] fp32
    __half* x1h = (__half*)(smem + SZ_F12 + SZ_STG);  // [128][LDX] half

    __shared__ int   s_col[M_TILE];
    __shared__ int   s_row[M_TILE];
    __shared__ float b1s[512];
    __shared__ float b2s[128];
    __shared__ float W3s[128];

    const int tid  = threadIdx.x;
    const int base = blockIdx.x * M_TILE;

    // ---- indices + biases -------------------------------------------------
    if (tid < M_TILE) {
        int e = base + tid;
        s_col[tid] = (e < E) ? edge_index[e] : -1;
        s_row[tid] = (e < E) ? edge_index[E + e] : -1;
    } else {
        int n = tid - M_TILE;
        b2s[n] = b2[n];
        W3s[n] = W3[n];
    }
    {
        int n = tid * 2;
        b1s[n]     = b1[n];
        b1s[n + 1] = b1[n + 1];
    }
    __syncthreads();

    // ---- gather f12 as half -------------------------------------------------
    for (int i = tid; i < M_TILE * 64; i += THREADS) {
        int m = i >> 6;
        int q = i & 63;                 // float4 group within 256-float row
        int idx = (q < 32) ? s_col[m] : s_row[m];
        int qq  = (q < 32) ? q : (q - 32);
        float4 v;
        if (idx >= 0)
            v = ((const float4*)(emb + (long long)idx * 128))[qq];
        else
            v = make_float4(0.f, 0.f, 0.f, 0.f);
        __half2* dst = (__half2*)(f12 + m * LDF + q * 4);
        dst[0] = __floats2half2_rn(v.x, v.y);
        dst[1] = __floats2half2_rn(v.z, v.w);
    }
    __syncthreads();

    // ---- warp tiling: 2 (M) x 4 (N); warp tile 64x32 ------------------------
    const int w  = tid >> 5;
    const int wm = (w & 1) * 64;
    const int wn = (w >> 1) * 32;

    wmma::fragment<wmma::accumulator, 16, 16, 16, float> acc2[4][2];
    #pragma unroll
    for (int i = 0; i < 4; ++i)
        #pragma unroll
        for (int j = 0; j < 2; ++j)
            wmma::fill_fragment(acc2[i][j], 0.0f);

    #pragma unroll 1
    for (int c = 0; c < 4; ++c) {
        // ----- layer 1 chunk: acc1 = f12 @ W1H[:, c*128 + wn..] -------------
        wmma::fragment<wmma::accumulator, 16, 16, 16, float> acc1[4][2];
        #pragma unroll
        for (int i = 0; i < 4; ++i)
            #pragma unroll
            for (int j = 0; j < 2; ++j)
                wmma::fill_fragment(acc1[i][j], 0.0f);

        #pragma unroll 4
        for (int k = 0; k < 256; k += 16) {
            wmma::fragment<wmma::matrix_b, 16, 16, 16, __half, wmma::row_major> bf[2];
            #pragma unroll
            for (int j = 0; j < 2; ++j)
                wmma::load_matrix_sync(bf[j], g_W1H + (size_t)k * 512 + c * 128 + wn + j * 16, 512);
            wmma::fragment<wmma::matrix_a, 16, 16, 16, __half, wmma::row_major> a[4];
            #pragma unroll
            for (int i = 0; i < 4; ++i)
                wmma::load_matrix_sync(a[i], f12 + (wm + i * 16) * LDF + k, LDF);
            #pragma unroll
            for (int i = 0; i < 4; ++i)
                #pragma unroll
                for (int j = 0; j < 2; ++j)
                    wmma::mma_sync(acc1[i][j], a[i], bf[j], acc1[i][j]);
        }

        // x1h may still be read by previous chunk's layer 2
        __syncthreads();

        #pragma unroll
        for (int i = 0; i < 4; ++i)
            #pragma unroll
            for (int j = 0; j < 2; ++j)
                wmma::store_matrix_sync(stg + (wm + i * 16) * LDS + wn + j * 16,
                                        acc1[i][j], LDS, wmma::mem_row_major);
        __syncthreads();

        // ----- bias + relu, fp32 staging -> half x1h -------------------------
        for (int i = tid; i < 128 * 32; i += THREADS) {
            int m  = i >> 5;
            int nq = i & 31;            // 4-float group within 128
            float4 v = *(float4*)(stg + m * LDS + nq * 4);
            const float* bb = b1s + c * 128 + nq * 4;
            float r0 = fmaxf(v.x + bb[0], 0.f);
            float r1 = fmaxf(v.y + bb[1], 0.f);
            float r2 = fmaxf(v.z + bb[2], 0.f);
            float r3 = fmaxf(v.w + bb[3], 0.f);
            __half2* dst = (__half2*)(x1h + m * LDX + nq * 4);
            dst[0] = __floats2half2_rn(r0, r1);
            dst[1] = __floats2half2_rn(r2, r3);
        }
        __syncthreads();

        // ----- layer 2 partial: acc2 += x1h @ W2H[c*128.., wn..] -------------
        #pragma unroll 4
        for (int k = 0; k < 128; k += 16) {
            wmma::fragment<wmma::matrix_b, 16, 16, 16, __half, wmma::row_major> bf[2];
            #pragma unroll
            for (int j = 0; j < 2; ++j)
                wmma::load_matrix_sync(bf[j], g_W2H + (size_t)(c * 128 + k) * 128 + wn + j * 16, 128);
            wmma::fragment<wmma::matrix_a, 16, 16, 16, __half, wmma::row_major> a[4];
            #pragma unroll
            for (int i = 0; i < 4; ++i)
                wmma::load_matrix_sync(a[i], x1h + (wm + i * 16) * LDX + k, LDX);
            #pragma unroll
            for (int i = 0; i < 4; ++i)
                #pragma unroll
                for (int j = 0; j < 2; ++j)
                    wmma::mma_sync(acc2[i][j], a[i], bf[j], acc2[i][j]);
        }
    }

    // ---- x2 (fp32) -> staging ------------------------------------------------
    __syncthreads();
    #pragma unroll
    for (int i = 0; i < 4; ++i)
        #pragma unroll
        for (int j = 0; j < 2; ++j)
            wmma::store_matrix_sync(stg + (wm + i * 16) * LDS + wn + j * 16,
                                    acc2[i][j], LDS, wmma::mem_row_major);
    __syncthreads();

    // ---- layer 3: 2 threads per edge ------------------------------------------
    {
        int m = tid >> 1;
        int h = tid & 1;
        const float* xr = stg + m * LDS + h * 64;
        const float* bb = b2s + h * 64;
        const float* ww = W3s + h * 64;
        float s = 0.0f;
        #pragma unroll 8
        for (int n = 0; n < 64; ++n) {
            float v = fmaxf(xr[n] + bb[n], 0.0f);
            s += v * ww[n];
        }
        s += __shfl_xor_sync(0xffffffffu, s, 1);
        int e = base + m;
        if (h == 0 && e < E)
            out[e] = s + __ldg(b3);
    }
}

extern "C" void kernel_launch(void* const* d_in, const int* in_sizes, int n_in,
                              void* d_out, int out_size)
{
    const float* emb = (const float*)d_in[0];
    const int*   ei  = (const int*)d_in[1];     // int32 (JAX x64 disabled)
    const float* W1  = (const float*)d_in[2];
    const float* b1  = (const float*)d_in[3];
    const float* W2  = (const float*)d_in[4];
    const float* b2  = (const float*)d_in[5];
    const float* W3  = (const float*)d_in[6];
    const float* b3  = (const float*)d_in[7];
    float* out = (float*)d_out;

    const int E = out_size;   // output is [E,1] float32

    prep_weights<<<(256*512 + 512*128 + 255) / 256, 256>>>(W1, W2);

    cudaFuncSetAttribute(extractor_mlp_kernel,
                         cudaFuncAttributeMaxDynamicSharedMemorySize, SMEM_DYN);

    int grid = (E + M_TILE - 1) / M_TILE;
    extractor_mlp_kernel<<<grid, THREADS, SMEM_DYN>>>(
        emb, ei, b1, b2, W3, b3, out, E);
}

// round 7
// speedup vs baseline: 4.5543x; 2.0848x over previous
#include <cuda_runtime.h>
#include <cuda_fp16.h>
#include <cstdint>

// ---------------------------------------------------------------------------
// Fused ExtractorMLP, raw mma.sync.m16n8k16 (fp16 in, fp32 acc).
//  - relu+bias on layer-1 accumulators done IN REGISTERS (ISA-defined acc
//    fragment layout), half2 stored directly to x1h: no fp32 staging buffer.
//  - Weights pre-packed into exact B-fragment order (uint4 per lane) so every
//    B operand is a single coalesced LDG.128: no smem staging, no strided LDG.
//  - Layer-3 (dot with W3) computed from acc2 fragments in registers.
// One CTA = 128 edges, 256 threads, warp grid 2(M)x4(N), warp tile 64x32.
// ---------------------------------------------------------------------------

#define M_TILE  128
#define THREADS 256
#define LDF 264          // f12 leading dim (halves): 528B stride, mod128=16
#define LDX 136          // x1h leading dim (halves): 272B stride, mod128=16
#define SZ_F12 (M_TILE * LDF * 2)
#define SZ_X1H (M_TILE * LDX * 2)
#define SMEM_DYN (SZ_F12 + SZ_X1H)

// fragment-packed weights:
// g_W1F[s][p][lane]: s = k-step (k=16s, 16 steps), p = n16-pair (32 pairs),
//   uint4 = {b0,b1 of n8-tile lo, b0,b1 of n8-tile hi} for mma m16n8k16.
__device__ uint4 g_W1F[16 * 32 * 32];   // 256 KB
__device__ uint4 g_W2F[32 * 8 * 32];    // 128 KB  (32 k-steps, 8 n16-pairs)

__device__ __forceinline__ uint32_t pk2f(float a, float b) {
    __half2 h = __floats2half2_rn(a, b);
    return *reinterpret_cast<uint32_t*>(&h);
}

__global__ void prep_weights(const float* __restrict__ W1,
                             const float* __restrict__ W2) {
    int j = blockIdx.x * blockDim.x + threadIdx.x;
    if (j < 16 * 32 * 32) {
        int s    = j >> 10;
        int p    = (j >> 5) & 31;
        int lane = j & 31;
        int k0 = s * 16 + (lane & 3) * 2;
        int n0 = p * 16 + (lane >> 2);
        uint4 v;
        v.x = pk2f(W1[k0 * 512 + n0],           W1[(k0 + 1) * 512 + n0]);
        v.y = pk2f(W1[(k0 + 8) * 512 + n0],     W1[(k0 + 9) * 512 + n0]);
        v.z = pk2f(W1[k0 * 512 + n0 + 8],       W1[(k0 + 1) * 512 + n0 + 8]);
        v.w = pk2f(W1[(k0 + 8) * 512 + n0 + 8], W1[(k0 + 9) * 512 + n0 + 8]);
        g_W1F[j] = v;
    } else {
        int j2 = j - 16 * 32 * 32;
        if (j2 < 32 * 8 * 32) {
            int S    = j2 >> 8;
            int q    = (j2 >> 5) & 7;
            int lane = j2 & 31;
            int k0 = S * 16 + (lane & 3) * 2;
            int n0 = q * 16 + (lane >> 2);
            uint4 v;
            v.x = pk2f(W2[k0 * 128 + n0],           W2[(k0 + 1) * 128 + n0]);
            v.y = pk2f(W2[(k0 + 8) * 128 + n0],     W2[(k0 + 9) * 128 + n0]);
            v.z = pk2f(W2[k0 * 128 + n0 + 8],       W2[(k0 + 1) * 128 + n0 + 8]);
            v.w = pk2f(W2[(k0 + 8) * 128 + n0 + 8], W2[(k0 + 9) * 128 + n0 + 8]);
            g_W2F[j2] = v;
        }
    }
}

__device__ __forceinline__ void ldsm_x4(uint32_t r[4], const __half* p) {
    uint32_t addr = (uint32_t)__cvta_generic_to_shared(p);
    asm volatile("ldmatrix.sync.aligned.m8n8.x4.shared.b16 {%0,%1,%2,%3}, [%4];"
                 : "=r"(r[0]), "=r"(r[1]), "=r"(r[2]), "=r"(r[3])
                 : "r"(addr));
}

__device__ __forceinline__ void mma16816(float c[4], const uint32_t a[4],
                                         uint32_t b0, uint32_t b1) {
    asm volatile(
        "mma.sync.aligned.m16n8k16.row.col.f32.f16.f16.f32 "
        "{%0,%1,%2,%3}, {%4,%5,%6,%7}, {%8,%9}, {%0,%1,%2,%3};"
        : "+f"(c[0]), "+f"(c[1]), "+f"(c[2]), "+f"(c[3])
        : "r"(a[0]), "r"(a[1]), "r"(a[2]), "r"(a[3]), "r"(b0), "r"(b1));
}

__global__ void __launch_bounds__(THREADS, 1)
extractor_mlp_kernel(const float* __restrict__ emb,
                     const int* __restrict__ edge_index,
                     const float* __restrict__ b1,
                     const float* __restrict__ b2,
                     const float* __restrict__ W3,
                     const float* __restrict__ b3,
                     float* __restrict__ out, int E)
{
    extern __shared__ char smem[];
    __half* f12 = (__half*)smem;                 // [128][LDF]
    __half* x1h = (__half*)(smem + SZ_F12);      // [128][LDX]

    __shared__ int   s_col[M_TILE];
    __shared__ int   s_row[M_TILE];
    __shared__ float b1s[512];
    __shared__ float b2s[128];
    __shared__ float W3s[128];
    __shared__ float sred[4 * 128];

    const int tid  = threadIdx.x;
    const int lane = tid & 31;
    const int w    = tid >> 5;
    const int wm   = (w & 1) * 64;    // M offset
    const int wn   = (w >> 1) * 32;   // N offset within 128-chunk
    const int wnp  = wn >> 4;         // n16-pair base
    const int base = blockIdx.x * M_TILE;

    // ---- indices + biases ------------------------------------------------
    if (tid < M_TILE) {
        int e = base + tid;
        s_col[tid] = (e < E) ? edge_index[e] : 0;
        s_row[tid] = (e < E) ? edge_index[E + e] : 0;
    } else {
        int n = tid - M_TILE;
        b2s[n] = b2[n];
        W3s[n] = W3[n];
    }
    b1s[tid]       = b1[tid];
    b1s[tid + 256] = b1[tid + 256];
    __syncthreads();

    // ---- gather f12 = [emb[col] | emb[row]] as half ------------------------
    for (int i = tid; i < M_TILE * 64; i += THREADS) {
        int m = i >> 6;
        int q = i & 63;
        int idx = (q < 32) ? s_col[m] : s_row[m];
        int qq  = (q < 32) ? q : (q - 32);
        float4 v = ((const float4*)(emb + (long long)idx * 128))[qq];
        uint32_t* dst = (uint32_t*)(f12 + m * LDF + q * 4);
        dst[0] = pk2f(v.x, v.y);
        dst[1] = pk2f(v.z, v.w);
    }
    __syncthreads();

    float acc2[4][4][4];
    #pragma unroll
    for (int mt = 0; mt < 4; ++mt)
        #pragma unroll
        for (int t8 = 0; t8 < 4; ++t8)
            #pragma unroll
            for (int r = 0; r < 4; ++r)
                acc2[mt][t8][r] = 0.0f;

    const int rowA = wm + (lane & 15);          // ldmatrix row base
    const int colA = (lane >> 4) * 8;           // ldmatrix col base (halves)
    const int g    = lane >> 2;                 // acc row group
    const int cp   = (lane & 3) * 2;            // acc col pair base

    #pragma unroll 1
    for (int c = 0; c < 4; ++c) {
        // ----- layer 1: acc1 = f12 @ W1[:, c*128 + wn .. +32] ---------------
        float acc1[4][4][4];
        #pragma unroll
        for (int mt = 0; mt < 4; ++mt)
            #pragma unroll
            for (int t8 = 0; t8 < 4; ++t8)
                #pragma unroll
                for (int r = 0; r < 4; ++r)
                    acc1[mt][t8][r] = 0.0f;

        #pragma unroll 2
        for (int ks = 0; ks < 16; ++ks) {
            uint4 B0 = g_W1F[(ks * 32 + c * 8 + wnp)     * 32 + lane];
            uint4 B1 = g_W1F[(ks * 32 + c * 8 + wnp + 1) * 32 + lane];
            #pragma unroll
            for (int mt = 0; mt < 4; ++mt) {
                uint32_t a[4];
                ldsm_x4(a, f12 + (rowA + mt * 16) * LDF + ks * 16 + colA);
                mma16816(acc1[mt][0], a, B0.x, B0.y);
                mma16816(acc1[mt][1], a, B0.z, B0.w);
                mma16816(acc1[mt][2], a, B1.x, B1.y);
                mma16816(acc1[mt][3], a, B1.z, B1.w);
            }
        }

        // previous chunk's layer-2 must be done reading x1h
        __syncthreads();

        // ----- bias + relu in registers, store half2 to x1h -----------------
        #pragma unroll
        for (int t8 = 0; t8 < 4; ++t8) {
            int col = wn + t8 * 8 + cp;                  // local col in chunk
            float bx = b1s[c * 128 + col];
            float by = b1s[c * 128 + col + 1];
            #pragma unroll
            for (int mt = 0; mt < 4; ++mt) {
                int ra = wm + mt * 16 + g;
                float r0 = fmaxf(acc1[mt][t8][0] + bx, 0.0f);
                float r1 = fmaxf(acc1[mt][t8][1] + by, 0.0f);
                float r2 = fmaxf(acc1[mt][t8][2] + bx, 0.0f);
                float r3 = fmaxf(acc1[mt][t8][3] + by, 0.0f);
                *(uint32_t*)(x1h + ra * LDX + col)       = pk2f(r0, r1);
                *(uint32_t*)(x1h + (ra + 8) * LDX + col) = pk2f(r2, r3);
            }
        }
        __syncthreads();

        // ----- layer 2 partial: acc2 += x1_c @ W2[c*128 .. , wn .. +32] -----
        #pragma unroll 2
        for (int ks = 0; ks < 8; ++ks) {
            int S = c * 8 + ks;
            uint4 C0 = g_W2F[(S * 8 + wnp)     * 32 + lane];
            uint4 C1 = g_W2F[(S * 8 + wnp + 1) * 32 + lane];
            #pragma unroll
            for (int mt = 0; mt < 4; ++mt) {
                uint32_t a[4];
                ldsm_x4(a, x1h + (rowA + mt * 16) * LDX + ks * 16 + colA);
                mma16816(acc2[mt][0], a, C0.x, C0.y);
                mma16816(acc2[mt][1], a, C0.z, C0.w);
                mma16816(acc2[mt][2], a, C1.x, C1.y);
                mma16816(acc2[mt][3], a, C1.z, C1.w);
            }
        }
    }

    // ---- layer 3 in registers: s = relu(x2 + b2) . W3 ----------------------
    #pragma unroll
    for (int mt = 0; mt < 4; ++mt) {
        float sA = 0.0f, sB = 0.0f;
        #pragma unroll
        for (int t8 = 0; t8 < 4; ++t8) {
            int col = wn + t8 * 8 + cp;
            float bx = b2s[col],     wx = W3s[col];
            float by = b2s[col + 1], wy = W3s[col + 1];
            sA += fmaxf(acc2[mt][t8][0] + bx, 0.0f) * wx
                + fmaxf(acc2[mt][t8][1] + by, 0.0f) * wy;
            sB += fmaxf(acc2[mt][t8][2] + bx, 0.0f) * wx
                + fmaxf(acc2[mt][t8][3] + by, 0.0f) * wy;
        }
        sA += __shfl_xor_sync(0xffffffffu, sA, 1);
        sA += __shfl_xor_sync(0xffffffffu, sA, 2);
        sB += __shfl_xor_sync(0xffffffffu, sB, 1);
        sB += __shfl_xor_sync(0xffffffffu, sB, 2);
        if ((lane & 3) == 0) {
            int r = wm + mt * 16 + g;
            sred[(w >> 1) * 128 + r]     = sA;
            sred[(w >> 1) * 128 + r + 8] = sB;
        }
    }
    __syncthreads();

    if (tid < M_TILE) {
        float v = sred[tid] + sred[128 + tid] + sred[256 + tid] + sred[384 + tid]
                + __ldg(b3);
        int e = base + tid;
        if (e < E) out[e] = v;
    }
}

extern "C" void kernel_launch(void* const* d_in, const int* in_sizes, int n_in,
                              void* d_out, int out_size)
{
    const float* emb = (const float*)d_in[0];
    const int*   ei  = (const int*)d_in[1];     // int32 (JAX x64 disabled)
    const float* W1  = (const float*)d_in[2];
    const float* b1  = (const float*)d_in[3];
    const float* W2  = (const float*)d_in[4];
    const float* b2  = (const float*)d_in[5];
    const float* W3  = (const float*)d_in[6];
    const float* b3  = (const float*)d_in[7];
    float* out = (float*)d_out;

    const int E = out_size;   // output is [E,1] float32

    prep_weights<<<(16*32*32 + 32*8*32 + 255) / 256, 256>>>(W1, W2);

    cudaFuncSetAttribute(extractor_mlp_kernel,
                         cudaFuncAttributeMaxDynamicSharedMemorySize, SMEM_DYN);

    int grid = (E + M_TILE - 1) / M_TILE;
    extractor_mlp_kernel<<<grid, THREADS, SMEM_DYN>>>(
        emb, ei, b1, b2, W3, b3, out, E);
}

// round 8
// speedup vs baseline: 5.0062x; 1.0992x over previous
#include <cuda_runtime.h>
#include <cuda_fp16.h>
#include <cstdint>

// ---------------------------------------------------------------------------
// Fused ExtractorMLP, raw mma.sync.m16n8k16 (fp16 in, fp32 acc).
// Round 8: 16 warps/CTA (512 threads), warp grid 4(M)x4(N), warp tile 32x32.
// Halves per-thread accumulator registers (fits 128-reg budget) and doubles
// warps/SM for latency hiding (occ 12.5% -> 25%).
// ---------------------------------------------------------------------------

#define M_TILE  128
#define THREADS 512
#define LDF 264          // f12 leading dim (halves): 528B stride, mod128=16
#define LDX 136          // x1h leading dim (halves): 272B stride, mod128=16
#define SZ_F12 (M_TILE * LDF * 2)
#define SZ_X1H (M_TILE * LDX * 2)
#define SMEM_DYN (SZ_F12 + SZ_X1H)

// fragment-packed weights:
// g_W1F[s][p][lane]: s = k-step (16 steps), p = n16-pair (32 pairs),
//   uint4 = {b0,b1 of n8-tile lo, b0,b1 of n8-tile hi} for mma m16n8k16.
__device__ uint4 g_W1F[16 * 32 * 32];   // 256 KB
__device__ uint4 g_W2F[32 * 8 * 32];    // 128 KB  (32 k-steps, 8 n16-pairs)

__device__ __forceinline__ uint32_t pk2f(float a, float b) {
    __half2 h = __floats2half2_rn(a, b);
    return *reinterpret_cast<uint32_t*>(&h);
}

__global__ void prep_weights(const float* __restrict__ W1,
                             const float* __restrict__ W2) {
    int j = blockIdx.x * blockDim.x + threadIdx.x;
    if (j < 16 * 32 * 32) {
        int s    = j >> 10;
        int p    = (j >> 5) & 31;
        int lane = j & 31;
        int k0 = s * 16 + (lane & 3) * 2;
        int n0 = p * 16 + (lane >> 2);
        uint4 v;
        v.x = pk2f(W1[k0 * 512 + n0],           W1[(k0 + 1) * 512 + n0]);
        v.y = pk2f(W1[(k0 + 8) * 512 + n0],     W1[(k0 + 9) * 512 + n0]);
        v.z = pk2f(W1[k0 * 512 + n0 + 8],       W1[(k0 + 1) * 512 + n0 + 8]);
        v.w = pk2f(W1[(k0 + 8) * 512 + n0 + 8], W1[(k0 + 9) * 512 + n0 + 8]);
        g_W1F[j] = v;
    } else {
        int j2 = j - 16 * 32 * 32;
        if (j2 < 32 * 8 * 32) {
            int S    = j2 >> 8;
            int q    = (j2 >> 5) & 7;
            int lane = j2 & 31;
            int k0 = S * 16 + (lane & 3) * 2;
            int n0 = q * 16 + (lane >> 2);
            uint4 v;
            v.x = pk2f(W2[k0 * 128 + n0],           W2[(k0 + 1) * 128 + n0]);
            v.y = pk2f(W2[(k0 + 8) * 128 + n0],     W2[(k0 + 9) * 128 + n0]);
            v.z = pk2f(W2[k0 * 128 + n0 + 8],       W2[(k0 + 1) * 128 + n0 + 8]);
            v.w = pk2f(W2[(k0 + 8) * 128 + n0 + 8], W2[(k0 + 9) * 128 + n0 + 8]);
            g_W2F[j2] = v;
        }
    }
}

__device__ __forceinline__ void ldsm_x4(uint32_t r[4], const __half* p) {
    uint32_t addr = (uint32_t)__cvta_generic_to_shared(p);
    asm volatile("ldmatrix.sync.aligned.m8n8.x4.shared.b16 {%0,%1,%2,%3}, [%4];"
                 : "=r"(r[0]), "=r"(r[1]), "=r"(r[2]), "=r"(r[3])
                 : "r"(addr));
}

__device__ __forceinline__ void mma16816(float c[4], const uint32_t a[4],
                                         uint32_t b0, uint32_t b1) {
    asm volatile(
        "mma.sync.aligned.m16n8k16.row.col.f32.f16.f16.f32 "
        "{%0,%1,%2,%3}, {%4,%5,%6,%7}, {%8,%9}, {%0,%1,%2,%3};"
        : "+f"(c[0]), "+f"(c[1]), "+f"(c[2]), "+f"(c[3])
        : "r"(a[0]), "r"(a[1]), "r"(a[2]), "r"(a[3]), "r"(b0), "r"(b1));
}

__global__ void __launch_bounds__(THREADS, 1)
extractor_mlp_kernel(const float* __restrict__ emb,
                     const int* __restrict__ edge_index,
                     const float* __restrict__ b1,
                     const float* __restrict__ b2,
                     const float* __restrict__ W3,
                     const float* __restrict__ b3,
                     float* __restrict__ out, int E)
{
    extern __shared__ char smem[];
    __half* f12 = (__half*)smem;                 // [128][LDF]
    __half* x1h = (__half*)(smem + SZ_F12);      // [128][LDX]

    __shared__ int   s_col[M_TILE];
    __shared__ int   s_row[M_TILE];
    __shared__ float b1s[512];
    __shared__ float b2s[128];
    __shared__ float W3s[128];
    __shared__ float sred[4 * 128];

    const int tid  = threadIdx.x;
    const int lane = tid & 31;
    const int w    = tid >> 5;        // 0..15
    const int wm   = (w & 3) * 32;    // M offset (4 groups)
    const int wn   = (w >> 2) * 32;   // N offset within 128-chunk (4 groups)
    const int wnp  = wn >> 4;         // n16-pair base
    const int base = blockIdx.x * M_TILE;

    // ---- indices + biases ------------------------------------------------
    if (tid < M_TILE) {
        int e = base + tid;
        s_col[tid] = (e < E) ? edge_index[e] : 0;
        s_row[tid] = (e < E) ? edge_index[E + e] : 0;
    } else if (tid < 2 * M_TILE) {
        int n = tid - M_TILE;
        b2s[n] = b2[n];
        W3s[n] = W3[n];
    }
    b1s[tid] = b1[tid];
    __syncthreads();

    // ---- gather f12 = [emb[col] | emb[row]] as half ------------------------
    for (int i = tid; i < M_TILE * 64; i += THREADS) {
        int m = i >> 6;
        int q = i & 63;
        int idx = (q < 32) ? s_col[m] : s_row[m];
        int qq  = (q < 32) ? q : (q - 32);
        float4 v = ((const float4*)(emb + (long long)idx * 128))[qq];
        uint32_t* dst = (uint32_t*)(f12 + m * LDF + q * 4);
        dst[0] = pk2f(v.x, v.y);
        dst[1] = pk2f(v.z, v.w);
    }
    __syncthreads();

    float acc2[2][4][4];
    #pragma unroll
    for (int mt = 0; mt < 2; ++mt)
        #pragma unroll
        for (int t8 = 0; t8 < 4; ++t8)
            #pragma unroll
            for (int r = 0; r < 4; ++r)
                acc2[mt][t8][r] = 0.0f;

    const int rowA = wm + (lane & 15);          // ldmatrix row base
    const int colA = (lane >> 4) * 8;           // ldmatrix col base (halves)
    const int g    = lane >> 2;                 // acc row group
    const int cp   = (lane & 3) * 2;            // acc col pair base

    #pragma unroll 1
    for (int c = 0; c < 4; ++c) {
        // ----- layer 1: acc1 = f12 @ W1[:, c*128 + wn .. +32] ---------------
        float acc1[2][4][4];
        #pragma unroll
        for (int mt = 0; mt < 2; ++mt)
            #pragma unroll
            for (int t8 = 0; t8 < 4; ++t8)
                #pragma unroll
                for (int r = 0; r < 4; ++r)
                    acc1[mt][t8][r] = 0.0f;

        #pragma unroll 2
        for (int ks = 0; ks < 16; ++ks) {
            uint4 B0 = g_W1F[(ks * 32 + c * 8 + wnp)     * 32 + lane];
            uint4 B1 = g_W1F[(ks * 32 + c * 8 + wnp + 1) * 32 + lane];
            #pragma unroll
            for (int mt = 0; mt < 2; ++mt) {
                uint32_t a[4];
                ldsm_x4(a, f12 + (rowA + mt * 16) * LDF + ks * 16 + colA);
                mma16816(acc1[mt][0], a, B0.x, B0.y);
                mma16816(acc1[mt][1], a, B0.z, B0.w);
                mma16816(acc1[mt][2], a, B1.x, B1.y);
                mma16816(acc1[mt][3], a, B1.z, B1.w);
            }
        }

        // previous chunk's layer-2 must be done reading x1h
        __syncthreads();

        // ----- bias + relu in registers, store half2 to x1h -----------------
        #pragma unroll
        for (int t8 = 0; t8 < 4; ++t8) {
            int col = wn + t8 * 8 + cp;                  // local col in chunk
            float bx = b1s[c * 128 + col];
            float by = b1s[c * 128 + col + 1];
            #pragma unroll
            for (int mt = 0; mt < 2; ++mt) {
                int ra = wm + mt * 16 + g;
                float r0 = fmaxf(acc1[mt][t8][0] + bx, 0.0f);
                float r1 = fmaxf(acc1[mt][t8][1] + by, 0.0f);
                float r2 = fmaxf(acc1[mt][t8][2] + bx, 0.0f);
                float r3 = fmaxf(acc1[mt][t8][3] + by, 0.0f);
                *(uint32_t*)(x1h + ra * LDX + col)       = pk2f(r0, r1);
                *(uint32_t*)(x1h + (ra + 8) * LDX + col) = pk2f(r2, r3);
            }
        }
        __syncthreads();

        // ----- layer 2 partial: acc2 += x1_c @ W2[c*128 .. , wn .. +32] -----
        #pragma unroll 2
        for (int ks = 0; ks < 8; ++ks) {
            int S = c * 8 + ks;
            uint4 C0 = g_W2F[(S * 8 + wnp)     * 32 + lane];
            uint4 C1 = g_W2F[(S * 8 + wnp + 1) * 32 + lane];
            #pragma unroll
            for (int mt = 0; mt < 2; ++mt) {
                uint32_t a[4];
                ldsm_x4(a, x1h + (rowA + mt * 16) * LDX + ks * 16 + colA);
                mma16816(acc2[mt][0], a, C0.x, C0.y);
                mma16816(acc2[mt][1], a, C0.z, C0.w);
                mma16816(acc2[mt][2], a, C1.x, C1.y);
                mma16816(acc2[mt][3], a, C1.z, C1.w);
            }
        }
    }

    // ---- layer 3 in registers: s = relu(x2 + b2) . W3 ----------------------
    #pragma unroll
    for (int mt = 0; mt < 2; ++mt) {
        float sA = 0.0f, sB = 0.0f;
        #pragma unroll
        for (int t8 = 0; t8 < 4; ++t8) {
            int col = wn + t8 * 8 + cp;
            float bx = b2s[col],     wx = W3s[col];
            float by = b2s[col + 1], wy = W3s[col + 1];
            sA += fmaxf(acc2[mt][t8][0] + bx, 0.0f) * wx
                + fmaxf(acc2[mt][t8][1] + by, 0.0f) * wy;
            sB += fmaxf(acc2[mt][t8][2] + bx, 0.0f) * wx
                + fmaxf(acc2[mt][t8][3] + by, 0.0f) * wy;
        }
        sA += __shfl_xor_sync(0xffffffffu, sA, 1);
        sA += __shfl_xor_sync(0xffffffffu, sA, 2);
        sB += __shfl_xor_sync(0xffffffffu, sB, 1);
        sB += __shfl_xor_sync(0xffffffffu, sB, 2);
        if ((lane & 3) == 0) {
            int r = wm + mt * 16 + g;
            sred[(w >> 2) * 128 + r]     = sA;
            sred[(w >> 2) * 128 + r + 8] = sB;
        }
    }
    __syncthreads();

    if (tid < M_TILE) {
        float v = sred[tid] + sred[128 + tid] + sred[256 + tid] + sred[384 + tid]
                + __ldg(b3);
        int e = base + tid;
        if (e < E) out[e] = v;
    }
}

extern "C" void kernel_launch(void* const* d_in, const int* in_sizes, int n_in,
                              void* d_out, int out_size)
{
    const float* emb = (const float*)d_in[0];
    const int*   ei  = (const int*)d_in[1];     // int32 (JAX x64 disabled)
    const float* W1  = (const float*)d_in[2];
    const float* b1  = (const float*)d_in[3];
    const float* W2  = (const float*)d_in[4];
    const float* b2  = (const float*)d_in[5];
    const float* W3  = (const float*)d_in[6];
    const float* b3  = (const float*)d_in[7];
    float* out = (float*)d_out;

    const int E = out_size;   // output is [E,1] float32

    prep_weights<<<(16*32*32 + 32*8*32 + 255) / 256, 256>>>(W1, W2);

    cudaFuncSetAttribute(extractor_mlp_kernel,
                         cudaFuncAttributeMaxDynamicSharedMemorySize, SMEM_DYN);

    int grid = (E + M_TILE - 1) / M_TILE;
    extractor_mlp_kernel<<<grid, THREADS, SMEM_DYN>>>(
        emb, ei, b1, b2, W3, b3, out, E);
}